// round 14
// baseline (speedup 1.0000x reference)
#include <cuda_runtime.h>
#include <cuda_bf16.h>
#include <math.h>
#include <stdint.h>

// GCNII forward: fused spmm+GEMM layer kernel with ping-pong activation
// buffers (fixes inter-CTA race of round 13), f32x2 packed FMA inner loops.
#define NNODES 50000
#define NEDGES 800000
#define DIN 512
#define DH 128
#define DC 40
#define NLAYERS 8
#define NSCANB 49

// ---------------- device scratch ----------------
__device__ __align__(16) float g_xa  [NNODES * DH];
__device__ __align__(16) float g_xb  [NNODES * DH];
__device__ __align__(16) float g_h0  [NNODES * DH];
__device__ __align__(16) float g_Wp  [NLAYERS * DH * DH];
__device__ int   g_rowstart[NNODES + 1];
__device__ int   g_cursor  [NNODES];
__device__ int   g_col     [NEDGES];
__device__ float g_wval    [NEDGES];
__device__ int   g_blocksum[64];

struct Betas { float b[NLAYERS]; };

// f32x2 helpers
#define FMA2(d, a, b) \
    asm("fma.rn.f32x2 %0, %1, %2, %3;" : "=l"(d) : "l"(a), "l"(b), "l"(d))
__device__ __forceinline__ unsigned long long pack_dup(float x) {
    unsigned long long r;
    uint32_t u = __float_as_uint(x);
    asm("mov.b64 %0, {%1, %1};" : "=l"(r) : "r"(u));
    return r;
}
union F2U { float2 f; unsigned long long u; };

// ---------------- CSR build ----------------
__global__ void k_zero() {
    int i = blockIdx.x * blockDim.x + threadIdx.x;
    if (i < NNODES) g_cursor[i] = 0;
}
__global__ void k_hist(const int* __restrict__ dst) {
    int e = blockIdx.x * blockDim.x + threadIdx.x;
    if (e < NEDGES) atomicAdd(&g_cursor[dst[e]], 1);
}
__global__ void k_blocksum() {
    __shared__ int s[1024];
    int idx = blockIdx.x * 1024 + threadIdx.x;
    s[threadIdx.x] = (idx < NNODES) ? g_cursor[idx] : 0;
    __syncthreads();
    for (int off = 512; off > 0; off >>= 1) {
        if (threadIdx.x < off) s[threadIdx.x] += s[threadIdx.x + off];
        __syncthreads();
    }
    if (threadIdx.x == 0) g_blocksum[blockIdx.x] = s[0];
}
__global__ void k_scan_small() {
    int run = 0;
    for (int b = 0; b < NSCANB; b++) { int t = g_blocksum[b]; g_blocksum[b] = run; run += t; }
    g_rowstart[NNODES] = run;
}
__global__ void k_scan_final() {
    __shared__ int s[1024];
    int tid = threadIdx.x;
    int idx = blockIdx.x * 1024 + tid;
    int v = (idx < NNODES) ? g_cursor[idx] : 0;
    s[tid] = v;
    __syncthreads();
    for (int off = 1; off < 1024; off <<= 1) {
        int t = (tid >= off) ? s[tid - off] : 0;
        __syncthreads();
        s[tid] += t;
        __syncthreads();
    }
    int excl = ((tid > 0) ? s[tid - 1] : 0) + g_blocksum[blockIdx.x];
    if (idx < NNODES) { g_rowstart[idx] = excl; g_cursor[idx] = excl; }
}
__global__ void k_fill(const int* __restrict__ src, const int* __restrict__ dst,
                       const float* __restrict__ w) {
    int e = blockIdx.x * blockDim.x + threadIdx.x;
    if (e < NEDGES) {
        int d = dst[e];
        int pos = atomicAdd(&g_cursor[d], 1);
        g_col[pos]  = src[e];
        g_wval[pos] = w[e];
    }
}

// ---------------- W' = beta*W + (1-beta)*I ----------------
__global__ void k_prepw(const float* __restrict__ conv_w, Betas bb) {
    int idx = blockIdx.x * blockDim.x + threadIdx.x;
    if (idx >= NLAYERS * DH * DH) return;
    int l = idx >> 14;
    int rem = idx & 16383;
    int k = rem >> 7, n = rem & 127;
    float beta = bb.b[l];
    float v = beta * conv_w[idx];
    if (k == n) v += 1.0f - beta;
    g_Wp[idx] = v;
}

// ---------------- fc0 tiled SGEMM (f32x2): xa = h0 = relu(A @ B + bias) ----------------
__global__ __launch_bounds__(256) void k_gemm0(const float* __restrict__ A,
                                               const float* __restrict__ B,
                                               const float* __restrict__ bias) {
    const int AS_LD = 132;
    __shared__ float As[16 * AS_LD];
    __shared__ float Bs[16 * 128];

    int tid = threadIdx.x;
    int tx = tid & 15;
    int ty = tid >> 4;
    int row0 = blockIdx.x * 128;

    unsigned long long acc2[8][4];
#pragma unroll
    for (int i = 0; i < 8; i++)
#pragma unroll
        for (int j = 0; j < 4; j++) acc2[i][j] = 0ULL;

    for (int k0 = 0; k0 < DIN; k0 += 16) {
#pragma unroll
        for (int it = 0; it < 2; it++) {
            int idx = tid + it * 256;
            int r = idx >> 2;
            int q = idx & 3;
            int grow = row0 + r;
            float4 v = make_float4(0.f, 0.f, 0.f, 0.f);
            if (grow < NNODES)
                v = *reinterpret_cast<const float4*>(A + (size_t)grow * DIN + k0 + q * 4);
            As[(q * 4 + 0) * AS_LD + r] = v.x;
            As[(q * 4 + 1) * AS_LD + r] = v.y;
            As[(q * 4 + 2) * AS_LD + r] = v.z;
            As[(q * 4 + 3) * AS_LD + r] = v.w;
        }
#pragma unroll
        for (int it = 0; it < 2; it++) {
            int idx = tid + it * 256;
            int kk = idx >> 5;
            int nq = idx & 31;
            *reinterpret_cast<float4*>(Bs + kk * 128 + nq * 4) =
                *reinterpret_cast<const float4*>(B + (size_t)(k0 + kk) * 128 + nq * 4);
        }
        __syncthreads();

#pragma unroll
        for (int k = 0; k < 16; k++) {
            float a[8];
#pragma unroll
            for (int i = 0; i < 8; i++) a[i] = As[k * AS_LD + ty * 8 + i];
            unsigned long long au[8];
#pragma unroll
            for (int i = 0; i < 8; i++) au[i] = pack_dup(a[i]);
            unsigned long long bu[4];
#pragma unroll
            for (int j = 0; j < 4; j++) {
                F2U t;
                t.f = *reinterpret_cast<const float2*>(Bs + k * 128 + tx * 8 + j * 2);
                bu[j] = t.u;
            }
#pragma unroll
            for (int i = 0; i < 8; i++)
#pragma unroll
                for (int j = 0; j < 4; j++) FMA2(acc2[i][j], au[i], bu[j]);
        }
        __syncthreads();
    }

#pragma unroll
    for (int i = 0; i < 8; i++) {
        int grow = row0 + ty * 8 + i;
        if (grow < NNODES) {
#pragma unroll
            for (int j = 0; j < 4; j++) {
                int n = tx * 8 + j * 2;
                F2U t; t.u = acc2[i][j];
                float c0 = fmaxf(t.f.x + bias[n], 0.f);
                float c1 = fmaxf(t.f.y + bias[n + 1], 0.f);
                float2 o = make_float2(c0, c1);
                *reinterpret_cast<float2*>(g_xa + (size_t)grow * DH + n) = o;
                *reinterpret_cast<float2*>(g_h0 + (size_t)grow * DH + n) = o;
            }
        }
    }
}

// ---------------- fused layer: xout = relu((0.9*Ahat*xin + 0.1*h0) @ Wp[l]) ----------------
// Phase 1: warp-per-node CSR gather from xin -> supT (transposed, smem).
// Phase 2: f32x2 GEMM supT @ Wp -> xout. Ping-pong buffers: no inter-CTA race.
// 2 CTAs/SM so one CTA's gather overlaps the other's GEMM.
#define ST_LD 132
#define SM_LAYER_TOTAL (128 * ST_LD * 4 + 16 * 128 * 4)

__global__ __launch_bounds__(256, 2) void k_layer(int layer, int flip) {
    extern __shared__ float sm[];
    float* supT = sm;                                   // [128 k][132 m]
    float* Bs   = sm + 128 * ST_LD;                     // [16 k][128 n]

    const float* xin  = flip ? g_xb : g_xa;
    float*       xout = flip ? g_xa : g_xb;

    int tid = threadIdx.x, wid = tid >> 5, lane = tid & 31;
    int row0 = blockIdx.x * 128;

    // ---- phase 1: gather 128 rows, write transposed ----
#pragma unroll 1
    for (int t = 0; t < 16; t++) {
        int local = wid * 16 + t;
        int node = row0 + local;
        float4 o = make_float4(0.f, 0.f, 0.f, 0.f);
        if (node < NNODES) {
            int s = g_rowstart[node];
            int e = g_rowstart[node + 1];
            float4 acc = make_float4(0.f, 0.f, 0.f, 0.f);
            for (int base = s; base < e; base += 32) {
                int i = base + lane;
                int   c = (i < e) ? g_col[i]  : 0;
                float w = (i < e) ? g_wval[i] : 0.f;
                int cnt = min(32, e - base);
                for (int j = 0; j < cnt; j++) {
                    int   cj = __shfl_sync(0xffffffffu, c, j);
                    float wj = __shfl_sync(0xffffffffu, w, j);
                    float4 xv = *reinterpret_cast<const float4*>(xin + (size_t)cj * DH + lane * 4);
                    acc.x += wj * xv.x; acc.y += wj * xv.y;
                    acc.z += wj * xv.z; acc.w += wj * xv.w;
                }
            }
            float4 h = *reinterpret_cast<const float4*>(g_h0 + (size_t)node * DH + lane * 4);
            o.x = 0.9f * acc.x + 0.1f * h.x;
            o.y = 0.9f * acc.y + 0.1f * h.y;
            o.z = 0.9f * acc.z + 0.1f * h.z;
            o.w = 0.9f * acc.w + 0.1f * h.w;
        }
        int kbase = lane * 4;
        supT[(kbase + 0) * ST_LD + local] = o.x;
        supT[(kbase + 1) * ST_LD + local] = o.y;
        supT[(kbase + 2) * ST_LD + local] = o.z;
        supT[(kbase + 3) * ST_LD + local] = o.w;
    }

    // ---- phase 2: GEMM supT @ Wp[layer] ----
    const float* B = g_Wp + (size_t)layer * DH * DH;
    int tx = tid & 15;
    int ty = tid >> 4;

    unsigned long long acc2[8][4];
#pragma unroll
    for (int i = 0; i < 8; i++)
#pragma unroll
        for (int j = 0; j < 4; j++) acc2[i][j] = 0ULL;

#pragma unroll 1
    for (int k0 = 0; k0 < DH; k0 += 16) {
#pragma unroll
        for (int it = 0; it < 2; it++) {
            int idx = tid + it * 256;
            int kk = idx >> 5;
            int nq = idx & 31;
            *reinterpret_cast<float4*>(Bs + kk * 128 + nq * 4) =
                *reinterpret_cast<const float4*>(B + (size_t)(k0 + kk) * 128 + nq * 4);
        }
        __syncthreads();   // first iteration also closes phase 1

#pragma unroll
        for (int k = 0; k < 16; k++) {
            float a[8];
#pragma unroll
            for (int i = 0; i < 8; i++) a[i] = supT[(k0 + k) * ST_LD + ty * 8 + i];
            unsigned long long au[8];
#pragma unroll
            for (int i = 0; i < 8; i++) au[i] = pack_dup(a[i]);
            unsigned long long bu[4];
#pragma unroll
            for (int j = 0; j < 4; j++) {
                F2U t;
                t.f = *reinterpret_cast<const float2*>(Bs + k * 128 + tx * 8 + j * 2);
                bu[j] = t.u;
            }
#pragma unroll
            for (int i = 0; i < 8; i++)
#pragma unroll
                for (int j = 0; j < 4; j++) FMA2(acc2[i][j], au[i], bu[j]);
        }
        __syncthreads();
    }

#pragma unroll
    for (int i = 0; i < 8; i++) {
        int grow = row0 + ty * 8 + i;
        if (grow < NNODES) {
#pragma unroll
            for (int j = 0; j < 4; j++) {
                int n = tx * 8 + j * 2;
                F2U t; t.u = acc2[i][j];
                float2 o = make_float2(fmaxf(t.f.x, 0.f), fmaxf(t.f.y, 0.f));
                *reinterpret_cast<float2*>(xout + (size_t)grow * DH + n) = o;
            }
        }
    }
}

// ---------------- fc1: out = g_xa @ W + bias  ([N,128]x[128,40]) ----------------
__global__ __launch_bounds__(256) void k_fc1(const float* __restrict__ W,
                                             const float* __restrict__ bias,
                                             float* __restrict__ out) {
    __shared__ float xs[32 * 132];
    __shared__ float Ws[128 * 40];
    int tid = threadIdx.x;
    int row0 = blockIdx.x * 32;

    for (int i = tid; i < 128 * 40; i += 256) Ws[i] = W[i];
#pragma unroll
    for (int it = 0; it < 4; it++) {
        int idx = tid + it * 256;
        int r = idx >> 5;
        int q = idx & 31;
        int grow = row0 + r;
        float4 v = make_float4(0.f, 0.f, 0.f, 0.f);
        if (grow < NNODES)
            v = *reinterpret_cast<const float4*>(g_xa + (size_t)grow * DH + q * 4);
        xs[r * 132 + q * 4 + 0] = v.x;
        xs[r * 132 + q * 4 + 1] = v.y;
        xs[r * 132 + q * 4 + 2] = v.z;
        xs[r * 132 + q * 4 + 3] = v.w;
    }
    __syncthreads();

    int r  = tid >> 3;
    int cg = tid & 7;
    int c0 = cg * 5;
    float acc[5] = {0.f, 0.f, 0.f, 0.f, 0.f};
#pragma unroll 4
    for (int k = 0; k < 128; k++) {
        float a = xs[r * 132 + k];
#pragma unroll
        for (int j = 0; j < 5; j++) acc[j] += a * Ws[k * 40 + c0 + j];
    }
    int grow = row0 + r;
    if (grow < NNODES) {
#pragma unroll
        for (int j = 0; j < 5; j++)
            out[(size_t)grow * DC + c0 + j] = acc[j] + bias[c0 + j];
    }
}

// ---------------- host ----------------
extern "C" void kernel_launch(void* const* d_in, const int* in_sizes, int n_in,
                              void* d_out, int out_size) {
    const float* features   = (const float*)d_in[0];
    const int*   edge_index = (const int*)  d_in[1];
    const float* norm_A     = (const float*)d_in[2];
    const float* w_fc0      = (const float*)d_in[3];
    const float* b_fc0      = (const float*)d_in[4];
    const float* conv_w     = (const float*)d_in[5];
    const float* w_fc1      = (const float*)d_in[6];
    const float* b_fc1      = (const float*)d_in[7];
    float* out = (float*)d_out;

    const int* srcp = edge_index;
    const int* dstp = edge_index + NEDGES;

    cudaFuncSetAttribute(k_layer, cudaFuncAttributeMaxDynamicSharedMemorySize,
                         SM_LAYER_TOTAL);

    const int GEMM_BLOCKS = (NNODES + 127) / 128;   // 391

    // Launch order keeps the ncu target (4th launch) on the fc0 GEMM.
    k_zero<<<(NNODES + 255) / 256, 256>>>();
    k_hist<<<(NEDGES + 255) / 256, 256>>>(dstp);
    k_blocksum<<<NSCANB, 1024>>>();
    k_gemm0<<<GEMM_BLOCKS, 256>>>(features, w_fc0, b_fc0);   // <- profiled
    k_scan_small<<<1, 1>>>();
    k_scan_final<<<NSCANB, 1024>>>();
    k_fill<<<(NEDGES + 255) / 256, 256>>>(srcp, dstp, norm_A);

    Betas bb;
    for (int l = 0; l < NLAYERS; l++)
        bb.b[l] = (float)log(0.5 / (double)(l + 1) + 1.0);
    k_prepw<<<(NLAYERS * DH * DH + 255) / 256, 256>>>(conv_w, bb);

    // 8 fused GCNII layers, ping-pong buffers: even l reads xa->xb, odd xb->xa.
    // After 8 layers the result is in g_xa, which fc1 reads.
    for (int l = 0; l < NLAYERS; l++)
        k_layer<<<GEMM_BLOCKS, 256, SM_LAYER_TOTAL>>>(l, l & 1);

    // fc1
    k_fc1<<<(NNODES + 31) / 32, 256>>>(w_fc1, b_fc1, out);
}

// round 17
// speedup vs baseline: 1.2259x; 1.2259x over previous
#include <cuda_runtime.h>
#include <cuda_bf16.h>
#include <math.h>
#include <stdint.h>

// GCNII forward: separate spmm + double-buffered pipelined f32x2 SGEMM.
// Round-15: revert round-14 fusion (gather needs high occupancy); add
// register-prefetch + 2-stage smem pipeline to hide global latency in GEMMs.
#define NNODES 50000
#define NEDGES 800000
#define DIN 512
#define DH 128
#define DC 40
#define NLAYERS 8
#define NSCANB 49

// ---------------- device scratch ----------------
__device__ __align__(16) float g_x   [NNODES * DH];
__device__ __align__(16) float g_h0  [NNODES * DH];
__device__ __align__(16) float g_sup [NNODES * DH];
__device__ __align__(16) float g_Wp  [NLAYERS * DH * DH];
__device__ int   g_rowstart[NNODES + 1];
__device__ int   g_cursor  [NNODES];
__device__ int   g_col     [NEDGES];
__device__ float g_wval    [NEDGES];
__device__ int   g_blocksum[64];

struct Betas { float b[NLAYERS]; };

// f32x2 helpers
#define FMA2(d, a, b) \
    asm("fma.rn.f32x2 %0, %1, %2, %3;" : "=l"(d) : "l"(a), "l"(b), "l"(d))
__device__ __forceinline__ unsigned long long pack_dup(float x) {
    unsigned long long r;
    uint32_t u = __float_as_uint(x);
    asm("mov.b64 %0, {%1, %1};" : "=l"(r) : "r"(u));
    return r;
}
union F2U { float2 f; unsigned long long u; };
union F4U2 { float4 f; unsigned long long u[2]; };

// ---------------- CSR build ----------------
__global__ void k_zero() {
    int i = blockIdx.x * blockDim.x + threadIdx.x;
    if (i < NNODES) g_cursor[i] = 0;
}
__global__ void k_hist(const int* __restrict__ dst) {
    int e = blockIdx.x * blockDim.x + threadIdx.x;
    if (e < NEDGES) atomicAdd(&g_cursor[dst[e]], 1);
}
__global__ void k_blocksum() {
    __shared__ int s[1024];
    int idx = blockIdx.x * 1024 + threadIdx.x;
    s[threadIdx.x] = (idx < NNODES) ? g_cursor[idx] : 0;
    __syncthreads();
    for (int off = 512; off > 0; off >>= 1) {
        if (threadIdx.x < off) s[threadIdx.x] += s[threadIdx.x + off];
        __syncthreads();
    }
    if (threadIdx.x == 0) g_blocksum[blockIdx.x] = s[0];
}
__global__ void k_scan_small() {
    int run = 0;
    for (int b = 0; b < NSCANB; b++) { int t = g_blocksum[b]; g_blocksum[b] = run; run += t; }
    g_rowstart[NNODES] = run;
}
__global__ void k_scan_final() {
    __shared__ int s[1024];
    int tid = threadIdx.x;
    int idx = blockIdx.x * 1024 + tid;
    int v = (idx < NNODES) ? g_cursor[idx] : 0;
    s[tid] = v;
    __syncthreads();
    for (int off = 1; off < 1024; off <<= 1) {
        int t = (tid >= off) ? s[tid - off] : 0;
        __syncthreads();
        s[tid] += t;
        __syncthreads();
    }
    int excl = ((tid > 0) ? s[tid - 1] : 0) + g_blocksum[blockIdx.x];
    if (idx < NNODES) { g_rowstart[idx] = excl; g_cursor[idx] = excl; }
}
__global__ void k_fill(const int* __restrict__ src, const int* __restrict__ dst,
                       const float* __restrict__ w) {
    int e = blockIdx.x * blockDim.x + threadIdx.x;
    if (e < NEDGES) {
        int d = dst[e];
        int pos = atomicAdd(&g_cursor[d], 1);
        g_col[pos]  = src[e];
        g_wval[pos] = w[e];
    }
}

// ---------------- W' = beta*W + (1-beta)*I ----------------
__global__ void k_prepw(const float* __restrict__ conv_w, Betas bb) {
    int idx = blockIdx.x * blockDim.x + threadIdx.x;
    if (idx >= NLAYERS * DH * DH) return;
    int l = idx >> 14;
    int rem = idx & 16383;
    int k = rem >> 7, n = rem & 127;
    float beta = bb.b[l];
    float v = beta * conv_w[idx];
    if (k == n) v += 1.0f - beta;
    g_Wp[idx] = v;
}

// ---------------- spmm: sup = 0.9 * (A_hat x) + 0.1 * h0 ----------------
__global__ __launch_bounds__(256) void k_spmm() {
    int gw = (blockIdx.x * blockDim.x + threadIdx.x) >> 5;
    int lane = threadIdx.x & 31;
    if (gw >= NNODES) return;
    int s = g_rowstart[gw];
    int e = g_rowstart[gw + 1];
    float4 acc = make_float4(0.f, 0.f, 0.f, 0.f);
    for (int base = s; base < e; base += 32) {
        int i = base + lane;
        int   c = (i < e) ? g_col[i]  : 0;
        float w = (i < e) ? g_wval[i] : 0.f;
        int cnt = min(32, e - base);
        for (int j = 0; j < cnt; j++) {
            int   cj = __shfl_sync(0xffffffffu, c, j);
            float wj = __shfl_sync(0xffffffffu, w, j);
            float4 xv = *reinterpret_cast<const float4*>(g_x + (size_t)cj * DH + lane * 4);
            acc.x += wj * xv.x; acc.y += wj * xv.y;
            acc.z += wj * xv.z; acc.w += wj * xv.w;
        }
    }
    float4 h = *reinterpret_cast<const float4*>(g_h0 + (size_t)gw * DH + lane * 4);
    float4 o;
    o.x = 0.9f * acc.x + 0.1f * h.x;
    o.y = 0.9f * acc.y + 0.1f * h.y;
    o.z = 0.9f * acc.z + 0.1f * h.z;
    o.w = 0.9f * acc.w + 0.1f * h.w;
    *reinterpret_cast<float4*>(g_sup + (size_t)gw * DH + lane * 4) = o;
}

// ---------------- pipelined tiled SGEMM (f32x2): out = relu(A @ B [+ bias]) ----
// BM=128, BN=128, BK=16, 256 threads, 8x8/thread, 2-stage smem double buffer,
// register prefetch of next chunk's LDGs under current chunk's FMAs.
#define AS_LD 132

template <int KTOT, int MODE>
__global__ __launch_bounds__(256, 2) void k_gemm(const float* __restrict__ Ain,
                                                 const float* __restrict__ Bin,
                                                 const float* __restrict__ bias,
                                                 int layer) {
    __shared__ float As[2][16 * AS_LD];
    __shared__ float Bs[2][16 * 128];

    const float* A = (MODE == 1) ? g_sup : Ain;
    const float* B = (MODE == 1) ? (g_Wp + (size_t)layer * DH * DH) : Bin;

    int tid = threadIdx.x;
    int tx = tid & 15;          // n: 16 threads * 8
    int ty = tid >> 4;          // m: 16 threads * 8
    int row0 = blockIdx.x * 128;

    // per-thread load coordinates (2 float4 each for A and B)
    int ar[2], aq[2], bkk[2], bnq[2];
    bool aok[2];
#pragma unroll
    for (int it = 0; it < 2; it++) {
        int idx = tid + it * 256;
        ar[it] = idx >> 2;          // 0..127
        aq[it] = idx & 3;           // 0..3
        aok[it] = (row0 + ar[it]) < NNODES;
        bkk[it] = idx >> 5;         // 0..15
        bnq[it] = idx & 31;         // 0..31
    }

    unsigned long long acc2[8][4];
#pragma unroll
    for (int i = 0; i < 8; i++)
#pragma unroll
        for (int j = 0; j < 4; j++) acc2[i][j] = 0ULL;

    float4 pa[2], pb[2];

    // ---- load chunk 0 into regs ----
#pragma unroll
    for (int it = 0; it < 2; it++) {
        pa[it] = make_float4(0.f, 0.f, 0.f, 0.f);
        if (aok[it])
            pa[it] = *reinterpret_cast<const float4*>(
                A + (size_t)(row0 + ar[it]) * KTOT + aq[it] * 4);
        pb[it] = *reinterpret_cast<const float4*>(B + (size_t)bkk[it] * 128 + bnq[it] * 4);
    }
    // ---- store chunk 0 into buffer 0 ----
#pragma unroll
    for (int it = 0; it < 2; it++) {
        As[0][(aq[it] * 4 + 0) * AS_LD + ar[it]] = pa[it].x;
        As[0][(aq[it] * 4 + 1) * AS_LD + ar[it]] = pa[it].y;
        As[0][(aq[it] * 4 + 2) * AS_LD + ar[it]] = pa[it].z;
        As[0][(aq[it] * 4 + 3) * AS_LD + ar[it]] = pa[it].w;
        *reinterpret_cast<float4*>(&Bs[0][bkk[it] * 128 + bnq[it] * 4]) = pb[it];
    }
    __syncthreads();

    const int NC = KTOT / 16;
#pragma unroll 1
    for (int c = 0; c < NC; c++) {
        // prefetch next chunk's globals into regs (hidden under compute)
        if (c + 1 < NC) {
            int k0 = (c + 1) * 16;
#pragma unroll
            for (int it = 0; it < 2; it++) {
                pa[it] = make_float4(0.f, 0.f, 0.f, 0.f);
                if (aok[it])
                    pa[it] = *reinterpret_cast<const float4*>(
                        A + (size_t)(row0 + ar[it]) * KTOT + k0 + aq[it] * 4);
                pb[it] = *reinterpret_cast<const float4*>(
                    B + (size_t)(k0 + bkk[it]) * 128 + bnq[it] * 4);
            }
        }

        // compute current chunk
        const float* as = As[c & 1];
        const float* bs = Bs[c & 1];
#pragma unroll
        for (int k = 0; k < 16; k++) {
            float a[8];
#pragma unroll
            for (int i = 0; i < 8; i++) a[i] = as[k * AS_LD + ty * 8 + i];
            unsigned long long au[8];
#pragma unroll
            for (int i = 0; i < 8; i++) au[i] = pack_dup(a[i]);
            unsigned long long bu[4];
#pragma unroll
            for (int j = 0; j < 2; j++) {
                F4U2 t;
                t.f = *reinterpret_cast<const float4*>(bs + k * 128 + tx * 8 + j * 4);
                bu[j * 2 + 0] = t.u[0];
                bu[j * 2 + 1] = t.u[1];
            }
#pragma unroll
            for (int i = 0; i < 8; i++)
#pragma unroll
                for (int j = 0; j < 4; j++) FMA2(acc2[i][j], au[i], bu[j]);
        }
        __syncthreads();   // all threads done reading buf[(c+1)&1] (used at c-1)

        if (c + 1 < NC) {
            float* asn = As[(c + 1) & 1];
            float* bsn = Bs[(c + 1) & 1];
#pragma unroll
            for (int it = 0; it < 2; it++) {
                asn[(aq[it] * 4 + 0) * AS_LD + ar[it]] = pa[it].x;
                asn[(aq[it] * 4 + 1) * AS_LD + ar[it]] = pa[it].y;
                asn[(aq[it] * 4 + 2) * AS_LD + ar[it]] = pa[it].z;
                asn[(aq[it] * 4 + 3) * AS_LD + ar[it]] = pa[it].w;
                *reinterpret_cast<float4*>(&bsn[bkk[it] * 128 + bnq[it] * 4]) = pb[it];
            }
            __syncthreads();
        }
    }

    // ---- epilogue ----
#pragma unroll
    for (int i = 0; i < 8; i++) {
        int grow = row0 + ty * 8 + i;
        if (grow < NNODES) {
#pragma unroll
            for (int j = 0; j < 4; j++) {
                int n = tx * 8 + j * 2;
                F2U t; t.u = acc2[i][j];
                float c0 = t.f.x, c1 = t.f.y;
                if (MODE == 0) { c0 += bias[n]; c1 += bias[n + 1]; }
                c0 = fmaxf(c0, 0.f);
                c1 = fmaxf(c1, 0.f);
                float2 o = make_float2(c0, c1);
                *reinterpret_cast<float2*>(g_x + (size_t)grow * DH + n) = o;
                if (MODE == 0)
                    *reinterpret_cast<float2*>(g_h0 + (size_t)grow * DH + n) = o;
            }
        }
    }
}

// ---------------- fc1: out = g_x @ W + bias  ([N,128]x[128,40]) ----------------
__global__ __launch_bounds__(256) void k_fc1(const float* __restrict__ W,
                                             const float* __restrict__ bias,
                                             float* __restrict__ out) {
    __shared__ float xs[32 * 132];
    __shared__ float Ws[128 * 40];
    int tid = threadIdx.x;
    int row0 = blockIdx.x * 32;

    for (int i = tid; i < 128 * 40; i += 256) Ws[i] = W[i];
#pragma unroll
    for (int it = 0; it < 4; it++) {
        int idx = tid + it * 256;
        int r = idx >> 5;
        int q = idx & 31;
        int grow = row0 + r;
        float4 v = make_float4(0.f, 0.f, 0.f, 0.f);
        if (grow < NNODES)
            v = *reinterpret_cast<const float4*>(g_x + (size_t)grow * DH + q * 4);
        xs[r * 132 + q * 4 + 0] = v.x;
        xs[r * 132 + q * 4 + 1] = v.y;
        xs[r * 132 + q * 4 + 2] = v.z;
        xs[r * 132 + q * 4 + 3] = v.w;
    }
    __syncthreads();

    int r  = tid >> 3;
    int cg = tid & 7;
    int c0 = cg * 5;
    float acc[5] = {0.f, 0.f, 0.f, 0.f, 0.f};
#pragma unroll 4
    for (int k = 0; k < 128; k++) {
        float a = xs[r * 132 + k];
#pragma unroll
        for (int j = 0; j < 5; j++) acc[j] += a * Ws[k * 40 + c0 + j];
    }
    int grow = row0 + r;
    if (grow < NNODES) {
#pragma unroll
        for (int j = 0; j < 5; j++)
            out[(size_t)grow * DC + c0 + j] = acc[j] + bias[c0 + j];
    }
}

// ---------------- host ----------------
extern "C" void kernel_launch(void* const* d_in, const int* in_sizes, int n_in,
                              void* d_out, int out_size) {
    const float* features   = (const float*)d_in[0];
    const int*   edge_index = (const int*)  d_in[1];
    const float* norm_A     = (const float*)d_in[2];
    const float* w_fc0      = (const float*)d_in[3];
    const float* b_fc0      = (const float*)d_in[4];
    const float* conv_w     = (const float*)d_in[5];
    const float* w_fc1      = (const float*)d_in[6];
    const float* b_fc1      = (const float*)d_in[7];
    float* out = (float*)d_out;

    const int* srcp = edge_index;
    const int* dstp = edge_index + NEDGES;

    const int GEMM_BLOCKS = (NNODES + 127) / 128;   // 391

    // Launch order keeps the ncu target (4th launch) on the fc0 GEMM.
    k_zero<<<(NNODES + 255) / 256, 256>>>();
    k_hist<<<(NEDGES + 255) / 256, 256>>>(dstp);
    k_blocksum<<<NSCANB, 1024>>>();
    k_gemm<DIN, 0><<<GEMM_BLOCKS, 256>>>(features, w_fc0, b_fc0, 0);   // <- profiled
    k_scan_small<<<1, 1>>>();
    k_scan_final<<<NSCANB, 1024>>>();
    k_fill<<<(NEDGES + 255) / 256, 256>>>(srcp, dstp, norm_A);

    Betas bb;
    for (int l = 0; l < NLAYERS; l++)
        bb.b[l] = (float)log(0.5 / (double)(l + 1) + 1.0);
    k_prepw<<<(NLAYERS * DH * DH + 255) / 256, 256>>>(conv_w, bb);

    // 8 GCNII layers (separate spmm + pipelined GEMM)
    const int SPMM_BLOCKS = (NNODES * 32 + 255) / 256;
    for (int l = 0; l < NLAYERS; l++) {
        k_spmm<<<SPMM_BLOCKS, 256>>>();
        k_gemm<DH, 1><<<GEMM_BLOCKS, 256>>>(nullptr, nullptr, nullptr, l);
    }

    // fc1
    k_fc1<<<(NNODES + 31) / 32, 256>>>(w_fc1, b_fc1, out);
}